// round 5
// baseline (speedup 1.0000x reference)
#include <cuda_runtime.h>

#define NN    50000
#define EE    800000
#define HH    128
#define GG    128
#define OUTD  10
#define NHOPS 4

// ---------------- device scratch (static, no runtime allocation) ----------------
__device__ __align__(16) float d_h0[NN * HH];
__device__ __align__(16) float d_h1[NN * HH];
__device__ __align__(16) float d_g[NN * HH];
__device__ float d_dinv[NN];
__device__ int   d_degcnt[NN];
__device__ int   d_rowptr[NN + 1];
__device__ int   d_cursor[NN];
__device__ int   d_esrc[EE];
__device__ float d_sums[GG * OUTD];
__device__ float d_cnt[GG];
__device__ int   d_stride;     // 1 = int32 inputs, 2 = int64 inputs

__device__ __forceinline__ int clampi(int v, int lo, int hi) {
    return v < lo ? lo : (v > hi ? hi : v);
}

// ---------------- dtype detection: int32 vs int64 edge_index -------------------
// For int64 (LE), odd 32-bit words are the zero high halves (indices < 50000).
// For int32, 128 consecutive random indices all being zero is impossible.
__global__ void detect_kernel(const int* __restrict__ ei_words) {
    __shared__ int nonzero;
    if (threadIdx.x == 0) nonzero = 0;
    __syncthreads();
    int w = ei_words[2 * threadIdx.x + 1];   // odd word of pair threadIdx.x
    if (w != 0) atomicOr(&nonzero, 1);
    __syncthreads();
    if (threadIdx.x == 0) d_stride = nonzero ? 1 : 2;
}

// ---------------- zero per-launch state ----------------
__global__ void zero_kernel() {
    int i = blockIdx.x * blockDim.x + threadIdx.x;
    if (i < NN) { d_degcnt[i] = 0; d_cursor[i] = 0; }
    if (i < GG * OUTD) d_sums[i] = 0.0f;
    if (i < GG) d_cnt[i] = 0.0f;
}

// ---------------- in-degree count ----------------
__global__ void count_kernel(const int* __restrict__ ei) {
    int e = blockIdx.x * blockDim.x + threadIdx.x;
    if (e < EE) {
        int st = d_stride;
        int dst = clampi(ei[(size_t)st * (EE + e)], 0, NN - 1);
        atomicAdd(&d_degcnt[dst], 1);
    }
}

// ---------------- single-block exclusive scan -> rowptr, and dinv ----------------
__global__ void scan_build_kernel() {
    const int T = 1024;
    const int CH = (NN + T - 1) / T;   // 49
    int t = threadIdx.x;
    int base = t * CH;
    int s = 0;
    for (int i = 0; i < CH; i++) {
        int idx = base + i;
        if (idx < NN) s += d_degcnt[idx];
    }
    int lane = t & 31, wid = t >> 5;
    int incl = s;
    #pragma unroll
    for (int o = 1; o < 32; o <<= 1) {
        int y = __shfl_up_sync(0xffffffffu, incl, o);
        if (lane >= o) incl += y;
    }
    __shared__ int wsum[32];
    if (lane == 31) wsum[wid] = incl;
    __syncthreads();
    if (wid == 0) {
        int v = wsum[lane];
        int iv = v;
        #pragma unroll
        for (int o = 1; o < 32; o <<= 1) {
            int y = __shfl_up_sync(0xffffffffu, iv, o);
            if (lane >= o) iv += y;
        }
        wsum[lane] = iv - v;
    }
    __syncthreads();
    int excl = wsum[wid] + (incl - s);
    int run = excl;
    for (int i = 0; i < CH; i++) {
        int idx = base + i;
        if (idx < NN) {
            d_rowptr[idx] = run;
            int dg = d_degcnt[idx];
            run += dg;
            d_dinv[idx] = rsqrtf(1.0f + (float)dg);
        }
    }
    if (t == T - 1) d_rowptr[NN] = run;
}

// ---------------- scatter edges into CSR buckets ----------------
__global__ void scatter_kernel(const int* __restrict__ ei) {
    int e = blockIdx.x * blockDim.x + threadIdx.x;
    if (e < EE) {
        int st = d_stride;
        int dst = clampi(ei[(size_t)st * (EE + e)], 0, NN - 1);
        int src = clampi(ei[(size_t)st * e],        0, NN - 1);
        int pos = d_rowptr[dst] + atomicAdd(&d_cursor[dst], 1);
        if (pos >= 0 && pos < EE) d_esrc[pos] = src;
    }
}

// ---------------- GEMM: C[n,128] = (A[n,128] @ B[128,128] + bias) * scale ------
// 256 threads, 64-row tile. Static smem: A tile 32KB + B k-chunk 16KB = 48KB.
__global__ __launch_bounds__(256) void gemm128_kernel(
    const float* __restrict__ Aext, const float* __restrict__ B,
    const float* __restrict__ bias, int asel, int use_scale, int csel)
{
    __shared__ float As[64 * 128];   // 32 KB
    __shared__ float Bs[32 * 128];   // 16 KB

    const float* A = (asel == 0) ? Aext : (asel == 1 ? d_h0 : d_h1);
    float* C = (csel == 0) ? d_g : (csel == 1 ? d_h0 : d_h1);

    int tid = threadIdx.x;
    int row0 = blockIdx.x * 64;

    float4* As4 = (float4*)As;
    #pragma unroll
    for (int i = 0; i < 8; i++) {
        int idx = tid + 256 * i;
        int r = idx >> 5, c = idx & 31;
        int gr = row0 + r;
        As4[idx] = (gr < NN) ? ((const float4*)A)[(size_t)gr * 32 + c]
                             : make_float4(0.f, 0.f, 0.f, 0.f);
    }

    int tx = tid & 15, ty = tid >> 4;
    float acc[4][8];
    #pragma unroll
    for (int r = 0; r < 4; r++)
        #pragma unroll
        for (int c = 0; c < 8; c++) acc[r][c] = 0.0f;

    const float* Asr = As + (ty * 4) * 128;
    const float* Bsc = Bs + tx * 8;
    const float4* B4 = (const float4*)B;
    float4* Bs4 = (float4*)Bs;

    for (int kc = 0; kc < 4; kc++) {
        __syncthreads();
        #pragma unroll
        for (int i = 0; i < 4; i++) {
            int idx = tid + 256 * i;
            Bs4[idx] = B4[kc * 1024 + idx];
        }
        __syncthreads();

        #pragma unroll
        for (int k2 = 0; k2 < 32; k2++) {
            float4 b0 = *(const float4*)(Bsc + k2 * 128);
            float4 b1 = *(const float4*)(Bsc + k2 * 128 + 4);
            #pragma unroll
            for (int r = 0; r < 4; r++) {
                float a = Asr[r * 128 + kc * 32 + k2];
                acc[r][0] = fmaf(a, b0.x, acc[r][0]);
                acc[r][1] = fmaf(a, b0.y, acc[r][1]);
                acc[r][2] = fmaf(a, b0.z, acc[r][2]);
                acc[r][3] = fmaf(a, b0.w, acc[r][3]);
                acc[r][4] = fmaf(a, b1.x, acc[r][4]);
                acc[r][5] = fmaf(a, b1.y, acc[r][5]);
                acc[r][6] = fmaf(a, b1.z, acc[r][6]);
                acc[r][7] = fmaf(a, b1.w, acc[r][7]);
            }
        }
    }

    int col = tx * 8;
    float bb[8];
    #pragma unroll
    for (int c = 0; c < 8; c++) bb[c] = bias ? bias[col + c] : 0.0f;

    #pragma unroll
    for (int r = 0; r < 4; r++) {
        int gr = row0 + ty * 4 + r;
        if (gr < NN) {
            float s = use_scale ? d_dinv[gr] : 1.0f;
            float4 o0, o1;
            o0.x = (acc[r][0] + bb[0]) * s;
            o0.y = (acc[r][1] + bb[1]) * s;
            o0.z = (acc[r][2] + bb[2]) * s;
            o0.w = (acc[r][3] + bb[3]) * s;
            o1.x = (acc[r][4] + bb[4]) * s;
            o1.y = (acc[r][5] + bb[5]) * s;
            o1.z = (acc[r][6] + bb[6]) * s;
            o1.w = (acc[r][7] + bb[7]) * s;
            float4* Cp = (float4*)(C + (size_t)gr * HH + col);
            Cp[0] = o0;
            Cp[1] = o1;
        }
    }
}

// ---------------- neighborhood aggregation (gather-side, warp per node) --------
__global__ __launch_bounds__(256) void aggregate_kernel(
    const float* __restrict__ bias, int relu, int outsel)
{
    int node = blockIdx.x * 8 + (threadIdx.x >> 5);
    if (node >= NN) return;
    int lane = threadIdx.x & 31;
    float* out = (outsel == 1) ? d_h0 : d_h1;

    const float4* g4 = (const float4*)d_g;
    float4 acc = g4[(size_t)node * 32 + lane];   // self term

    int s = d_rowptr[node], e = d_rowptr[node + 1];
    for (int j = s; j < e; j += 32) {
        int src = (j + lane < e) ? d_esrc[j + lane] : 0;
        int cnt = min(32, e - j);
        for (int t = 0; t < cnt; t++) {
            int ss = __shfl_sync(0xffffffffu, src, t);
            float4 v = g4[(size_t)ss * 32 + lane];
            acc.x += v.x; acc.y += v.y; acc.z += v.z; acc.w += v.w;
        }
    }

    float di = d_dinv[node];
    float4 b4 = ((const float4*)bias)[lane];
    float4 o;
    o.x = fmaf(acc.x, di, b4.x);
    o.y = fmaf(acc.y, di, b4.y);
    o.z = fmaf(acc.z, di, b4.z);
    o.w = fmaf(acc.w, di, b4.w);
    if (relu) {
        o.x = fmaxf(o.x, 0.f); o.y = fmaxf(o.y, 0.f);
        o.z = fmaxf(o.z, 0.f); o.w = fmaxf(o.w, 0.f);
    }
    ((float4*)out)[(size_t)node * 32 + lane] = o;
}

// ---------------- classifier + global mean pool ----------------
__global__ __launch_bounds__(256) void cls_pool_kernel(
    const int* __restrict__ batch,
    const float* __restrict__ Wc, const float* __restrict__ bc, int hsel)
{
    __shared__ float sW[HH * OUTD];
    __shared__ float sB[OUTD];
    int tid = threadIdx.x;
    for (int i = tid; i < HH * OUTD; i += 256) sW[i] = Wc[i];
    if (tid < OUTD) sB[tid] = bc[tid];
    __syncthreads();

    const float* h = (hsel == 1) ? d_h0 : d_h1;
    int node = blockIdx.x * 8 + (tid >> 5);
    if (node >= NN) return;
    int lane = tid & 31;

    float hv[4];
    #pragma unroll
    for (int q = 0; q < 4; q++) hv[q] = h[(size_t)node * HH + q * 32 + lane];

    int d = (lane < OUTD) ? lane : 0;
    float acc = 0.0f;
    #pragma unroll 4
    for (int k = 0; k < 128; k++) {
        float hk = __shfl_sync(0xffffffffu, hv[k >> 5], k & 31);
        acc = fmaf(hk, sW[k * OUTD + d], acc);
    }
    int st = d_stride;
    int b = clampi(batch[(size_t)st * node], 0, GG - 1);
    if (lane < OUTD)  atomicAdd(&d_sums[b * OUTD + lane], acc + sB[lane]);
    if (lane == OUTD) atomicAdd(&d_cnt[b], 1.0f);
}

// ---------------- final divide ----------------
__global__ void finalize_kernel(float* __restrict__ out) {
    int i = blockIdx.x * blockDim.x + threadIdx.x;
    if (i < GG * OUTD) {
        float c = d_cnt[i / OUTD];
        out[i] = d_sums[i] / fmaxf(c, 1.0f);
    }
}

// ---------------- launch ----------------
extern "C" void kernel_launch(void* const* d_in, const int* in_sizes, int n_in,
                              void* d_out, int out_size) {
    const float* x      = (const float*)d_in[0];
    const int*   ei     = (const int*)d_in[1];     // int32 or int64 (auto-detected)
    const int*   batch  = (const int*)d_in[2];     // same dtype as edge_index
    const float* W_in   = (const float*)d_in[3];
    const float* b_in   = (const float*)d_in[4];
    const float* W_hops = (const float*)d_in[5];
    const float* b_hops = (const float*)d_in[6];
    const float* W_cls  = (const float*)d_in[7];
    const float* b_cls  = (const float*)d_in[8];
    float* out = (float*)d_out;

    detect_kernel<<<1, 128>>>(ei);
    zero_kernel<<<(NN + 255) / 256, 256>>>();
    count_kernel<<<(EE + 255) / 256, 256>>>(ei);
    scan_build_kernel<<<1, 1024>>>();
    scatter_kernel<<<(EE + 255) / 256, 256>>>(ei);

    const int GB = (NN + 63) / 64;
    // encoder: h0 = x @ W_in + b_in
    gemm128_kernel<<<GB, 256>>>(x, W_in, b_in, 0, 0, 1);

    int cur = 1;   // d_h0
    for (int hop = 0; hop < NHOPS; hop++) {
        int nxt = (cur == 1) ? 2 : 1;
        gemm128_kernel<<<GB, 256>>>(nullptr, W_hops + (size_t)hop * HH * HH,
                                    nullptr, cur, 1, 0);
        aggregate_kernel<<<(NN + 7) / 8, 256>>>(b_hops + hop * HH,
                                                hop < NHOPS - 1 ? 1 : 0, nxt);
        cur = nxt;
    }

    cls_pool_kernel<<<(NN + 7) / 8, 256>>>(batch, W_cls, b_cls, cur);
    finalize_kernel<<<(GG * OUTD + 255) / 256, 256>>>(out);
}

// round 6
// speedup vs baseline: 1.1235x; 1.1235x over previous
#include <cuda_runtime.h>

#define NN    50000
#define EE    800000
#define HH    128
#define GG    128
#define OUTD  10
#define NHOPS 4
#define NB    ((NN + 255) / 256)   // 196 scan blocks

// ---------------- device scratch (static, no runtime allocation) ----------------
__device__ __align__(16) float d_h0[NN * HH];
__device__ __align__(16) float d_h1[NN * HH];
__device__ __align__(16) float d_g[NN * HH];
__device__ float d_dinv[NN];
__device__ int   d_degcnt[NN];
__device__ int   d_rowptr[NN + 1];
__device__ int   d_cursor[NN];
__device__ int   d_esrc[EE];
__device__ float d_sums[GG * OUTD];
__device__ float d_cnt[GG];
__device__ int   d_stride;     // 1 = int32 inputs, 2 = int64 inputs
__device__ int   d_blksum[NB];
__device__ int   d_blkoff[NB];

__device__ __forceinline__ int clampi(int v, int lo, int hi) {
    return v < lo ? lo : (v > hi ? hi : v);
}

// ---------------- dtype detection: int32 vs int64 edge_index -------------------
__global__ void detect_kernel(const int* __restrict__ ei_words) {
    __shared__ int nonzero;
    if (threadIdx.x == 0) nonzero = 0;
    __syncthreads();
    int w = ei_words[2 * threadIdx.x + 1];
    if (w != 0) atomicOr(&nonzero, 1);
    __syncthreads();
    if (threadIdx.x == 0) d_stride = nonzero ? 1 : 2;
}

// ---------------- zero per-launch state ----------------
__global__ void zero_kernel() {
    int i = blockIdx.x * blockDim.x + threadIdx.x;
    if (i < NN) { d_degcnt[i] = 0; d_cursor[i] = 0; }
    if (i < GG * OUTD) d_sums[i] = 0.0f;
    if (i < GG) d_cnt[i] = 0.0f;
}

// ---------------- in-degree count ----------------
__global__ void count_kernel(const int* __restrict__ ei) {
    int e = blockIdx.x * blockDim.x + threadIdx.x;
    if (e < EE) {
        int st = d_stride;
        int dst = clampi(ei[(size_t)st * (EE + e)], 0, NN - 1);
        atomicAdd(&d_degcnt[dst], 1);
    }
}

// ---------------- scan stage A: per-block sums of degcnt ----------------
__global__ __launch_bounds__(256) void scanA_kernel() {
    int i = blockIdx.x * 256 + threadIdx.x;
    int v = (i < NN) ? d_degcnt[i] : 0;
    int lane = threadIdx.x & 31, wid = threadIdx.x >> 5;
    // warp reduce
    int s = v;
    #pragma unroll
    for (int o = 16; o > 0; o >>= 1) s += __shfl_down_sync(0xffffffffu, s, o);
    __shared__ int ws[8];
    if (lane == 0) ws[wid] = s;
    __syncthreads();
    if (threadIdx.x == 0) {
        int t = 0;
        #pragma unroll
        for (int w = 0; w < 8; w++) t += ws[w];
        d_blksum[blockIdx.x] = t;
    }
}

// ---------------- scan stage B: exclusive scan of 196 block sums ----------------
__global__ __launch_bounds__(256) void scanB_kernel() {
    __shared__ int s_a[256], s_b[256];
    int t = threadIdx.x;
    int v = (t < NB) ? d_blksum[t] : 0;
    s_a[t] = v;
    __syncthreads();
    int* cur = s_a; int* nxt = s_b;
    for (int off = 1; off < 256; off <<= 1) {
        int x = cur[t];
        if (t >= off) x += cur[t - off];
        nxt[t] = x;
        __syncthreads();
        int* tmp = cur; cur = nxt; nxt = tmp;
    }
    if (t < NB) d_blkoff[t] = cur[t] - v;   // exclusive
    if (t == 0) d_rowptr[NN] = EE;
}

// ---------------- scan stage C: final rowptr + dinv ----------------
__global__ __launch_bounds__(256) void scanC_kernel() {
    int i = blockIdx.x * 256 + threadIdx.x;
    int v = (i < NN) ? d_degcnt[i] : 0;
    int lane = threadIdx.x & 31, wid = threadIdx.x >> 5;
    int incl = v;
    #pragma unroll
    for (int o = 1; o < 32; o <<= 1) {
        int y = __shfl_up_sync(0xffffffffu, incl, o);
        if (lane >= o) incl += y;
    }
    __shared__ int ws[8];
    if (lane == 31) ws[wid] = incl;
    __syncthreads();
    int woff = 0;
    #pragma unroll
    for (int w = 0; w < 8; w++) woff += (w < wid) ? ws[w] : 0;
    if (i < NN) {
        d_rowptr[i] = d_blkoff[blockIdx.x] + woff + incl - v;
        d_dinv[i] = rsqrtf(1.0f + (float)v);
    }
}

// ---------------- scatter edges into CSR buckets ----------------
__global__ void scatter_kernel(const int* __restrict__ ei) {
    int e = blockIdx.x * blockDim.x + threadIdx.x;
    if (e < EE) {
        int st = d_stride;
        int dst = clampi(ei[(size_t)st * (EE + e)], 0, NN - 1);
        int src = clampi(ei[(size_t)st * e],        0, NN - 1);
        int pos = d_rowptr[dst] + atomicAdd(&d_cursor[dst], 1);
        if (pos >= 0 && pos < EE) d_esrc[pos] = src;
    }
}

// ---------------- GEMM: C[n,128] = (A[n,128] @ B[128,128] + bias) * scale ------
__global__ __launch_bounds__(256) void gemm128_kernel(
    const float* __restrict__ Aext, const float* __restrict__ B,
    const float* __restrict__ bias, int asel, int use_scale, int csel)
{
    __shared__ float As[64 * 128];   // 32 KB
    __shared__ float Bs[32 * 128];   // 16 KB

    const float* A = (asel == 0) ? Aext : (asel == 1 ? d_h0 : d_h1);
    float* C = (csel == 0) ? d_g : (csel == 1 ? d_h0 : d_h1);

    int tid = threadIdx.x;
    int row0 = blockIdx.x * 64;

    float4* As4 = (float4*)As;
    #pragma unroll
    for (int i = 0; i < 8; i++) {
        int idx = tid + 256 * i;
        int r = idx >> 5, c = idx & 31;
        int gr = row0 + r;
        As4[idx] = (gr < NN) ? ((const float4*)A)[(size_t)gr * 32 + c]
                             : make_float4(0.f, 0.f, 0.f, 0.f);
    }

    int tx = tid & 15, ty = tid >> 4;
    float acc[4][8];
    #pragma unroll
    for (int r = 0; r < 4; r++)
        #pragma unroll
        for (int c = 0; c < 8; c++) acc[r][c] = 0.0f;

    const float* Asr = As + (ty * 4) * 128;
    const float* Bsc = Bs + tx * 8;
    const float4* B4 = (const float4*)B;
    float4* Bs4 = (float4*)Bs;

    for (int kc = 0; kc < 4; kc++) {
        __syncthreads();
        #pragma unroll
        for (int i = 0; i < 4; i++) {
            int idx = tid + 256 * i;
            Bs4[idx] = B4[kc * 1024 + idx];
        }
        __syncthreads();

        #pragma unroll
        for (int k2 = 0; k2 < 32; k2++) {
            float4 b0 = *(const float4*)(Bsc + k2 * 128);
            float4 b1 = *(const float4*)(Bsc + k2 * 128 + 4);
            #pragma unroll
            for (int r = 0; r < 4; r++) {
                float a = Asr[r * 128 + kc * 32 + k2];
                acc[r][0] = fmaf(a, b0.x, acc[r][0]);
                acc[r][1] = fmaf(a, b0.y, acc[r][1]);
                acc[r][2] = fmaf(a, b0.z, acc[r][2]);
                acc[r][3] = fmaf(a, b0.w, acc[r][3]);
                acc[r][4] = fmaf(a, b1.x, acc[r][4]);
                acc[r][5] = fmaf(a, b1.y, acc[r][5]);
                acc[r][6] = fmaf(a, b1.z, acc[r][6]);
                acc[r][7] = fmaf(a, b1.w, acc[r][7]);
            }
        }
    }

    int col = tx * 8;
    float bb[8];
    #pragma unroll
    for (int c = 0; c < 8; c++) bb[c] = bias ? bias[col + c] : 0.0f;

    #pragma unroll
    for (int r = 0; r < 4; r++) {
        int gr = row0 + ty * 4 + r;
        if (gr < NN) {
            float s = use_scale ? d_dinv[gr] : 1.0f;
            float4 o0, o1;
            o0.x = (acc[r][0] + bb[0]) * s;
            o0.y = (acc[r][1] + bb[1]) * s;
            o0.z = (acc[r][2] + bb[2]) * s;
            o0.w = (acc[r][3] + bb[3]) * s;
            o1.x = (acc[r][4] + bb[4]) * s;
            o1.y = (acc[r][5] + bb[5]) * s;
            o1.z = (acc[r][6] + bb[6]) * s;
            o1.w = (acc[r][7] + bb[7]) * s;
            float4* Cp = (float4*)(C + (size_t)gr * HH + col);
            Cp[0] = o0;
            Cp[1] = o1;
        }
    }
}

// ---------------- neighborhood aggregation (gather-side, warp per node) --------
__global__ __launch_bounds__(256) void aggregate_kernel(
    const float* __restrict__ bias, int relu, int outsel)
{
    int node = blockIdx.x * 8 + (threadIdx.x >> 5);
    if (node >= NN) return;
    int lane = threadIdx.x & 31;
    float* out = (outsel == 1) ? d_h0 : d_h1;

    const float4* g4 = (const float4*)d_g;
    float4 acc = g4[(size_t)node * 32 + lane];   // self term

    int s = d_rowptr[node], e = d_rowptr[node + 1];
    for (int j = s; j < e; j += 32) {
        int src = (j + lane < e) ? d_esrc[j + lane] : 0;
        int cnt = min(32, e - j);
        for (int t = 0; t < cnt; t++) {
            int ss = __shfl_sync(0xffffffffu, src, t);
            float4 v = g4[(size_t)ss * 32 + lane];
            acc.x += v.x; acc.y += v.y; acc.z += v.z; acc.w += v.w;
        }
    }

    float di = d_dinv[node];
    float4 b4 = ((const float4*)bias)[lane];
    float4 o;
    o.x = fmaf(acc.x, di, b4.x);
    o.y = fmaf(acc.y, di, b4.y);
    o.z = fmaf(acc.z, di, b4.z);
    o.w = fmaf(acc.w, di, b4.w);
    if (relu) {
        o.x = fmaxf(o.x, 0.f); o.y = fmaxf(o.y, 0.f);
        o.z = fmaxf(o.z, 0.f); o.w = fmaxf(o.w, 0.f);
    }
    ((float4*)out)[(size_t)node * 32 + lane] = o;
}

// ---------------- classifier + global mean pool ----------------
__global__ __launch_bounds__(256) void cls_pool_kernel(
    const int* __restrict__ batch,
    const float* __restrict__ Wc, const float* __restrict__ bc, int hsel)
{
    __shared__ float sW[HH * OUTD];
    __shared__ float sB[OUTD];
    int tid = threadIdx.x;
    for (int i = tid; i < HH * OUTD; i += 256) sW[i] = Wc[i];
    if (tid < OUTD) sB[tid] = bc[tid];
    __syncthreads();

    const float* h = (hsel == 1) ? d_h0 : d_h1;
    int node = blockIdx.x * 8 + (tid >> 5);
    if (node >= NN) return;
    int lane = tid & 31;

    float hv[4];
    #pragma unroll
    for (int q = 0; q < 4; q++) hv[q] = h[(size_t)node * HH + q * 32 + lane];

    int d = (lane < OUTD) ? lane : 0;
    float acc = 0.0f;
    #pragma unroll 4
    for (int k = 0; k < 128; k++) {
        float hk = __shfl_sync(0xffffffffu, hv[k >> 5], k & 31);
        acc = fmaf(hk, sW[k * OUTD + d], acc);
    }
    int st = d_stride;
    int b = clampi(batch[(size_t)st * node], 0, GG - 1);
    if (lane < OUTD)  atomicAdd(&d_sums[b * OUTD + lane], acc + sB[lane]);
    if (lane == OUTD) atomicAdd(&d_cnt[b], 1.0f);
}

// ---------------- final divide ----------------
__global__ void finalize_kernel(float* __restrict__ out) {
    int i = blockIdx.x * blockDim.x + threadIdx.x;
    if (i < GG * OUTD) {
        float c = d_cnt[i / OUTD];
        out[i] = d_sums[i] / fmaxf(c, 1.0f);
    }
}

// ---------------- launch ----------------
extern "C" void kernel_launch(void* const* d_in, const int* in_sizes, int n_in,
                              void* d_out, int out_size) {
    const float* x      = (const float*)d_in[0];
    const int*   ei     = (const int*)d_in[1];
    const int*   batch  = (const int*)d_in[2];
    const float* W_in   = (const float*)d_in[3];
    const float* b_in   = (const float*)d_in[4];
    const float* W_hops = (const float*)d_in[5];
    const float* b_hops = (const float*)d_in[6];
    const float* W_cls  = (const float*)d_in[7];
    const float* b_cls  = (const float*)d_in[8];
    float* out = (float*)d_out;

    detect_kernel<<<1, 128>>>(ei);
    zero_kernel<<<(NN + 255) / 256, 256>>>();
    count_kernel<<<(EE + 255) / 256, 256>>>(ei);
    scanA_kernel<<<NB, 256>>>();
    scanB_kernel<<<1, 256>>>();
    scanC_kernel<<<NB, 256>>>();
    scatter_kernel<<<(EE + 255) / 256, 256>>>(ei);

    const int GB = (NN + 63) / 64;
    gemm128_kernel<<<GB, 256>>>(x, W_in, b_in, 0, 0, 1);

    int cur = 1;   // d_h0
    for (int hop = 0; hop < NHOPS; hop++) {
        int nxt = (cur == 1) ? 2 : 1;
        gemm128_kernel<<<GB, 256>>>(nullptr, W_hops + (size_t)hop * HH * HH,
                                    nullptr, cur, 1, 0);
        aggregate_kernel<<<(NN + 7) / 8, 256>>>(b_hops + hop * HH,
                                                hop < NHOPS - 1 ? 1 : 0, nxt);
        cur = nxt;
    }

    cls_pool_kernel<<<(NN + 7) / 8, 256>>>(batch, W_cls, b_cls, cur);
    finalize_kernel<<<(GG * OUTD + 255) / 256, 256>>>(out);
}

// round 8
// speedup vs baseline: 1.9309x; 1.7187x over previous
#include <cuda_runtime.h>
#include <cstdint>

#define NN    50000
#define EE    800000
#define HH    128
#define GG    128
#define OUTD  10
#define NHOPS 4
#define NB    ((NN + 255) / 256)   // 196 scan blocks

// ---------------- device scratch (static, no runtime allocation) ----------------
__device__ __align__(16) float d_h0[NN * HH];
__device__ __align__(16) float d_h1[NN * HH];
__device__ __align__(16) float d_g[NN * HH];
__device__ float d_dinv[NN];
__device__ int   d_degcnt[NN];
__device__ int   d_rowptr[NN + 1];
__device__ int   d_cursor[NN];
__device__ int   d_esrc[EE];
__device__ float d_sums[GG * OUTD];
__device__ float d_cnt[GG];
__device__ int   d_stride;     // 1 = int32 inputs, 2 = int64 inputs
__device__ int   d_blksum[NB];
__device__ int   d_blkoff[NB];

__device__ __forceinline__ int clampi(int v, int lo, int hi) {
    return v < lo ? lo : (v > hi ? hi : v);
}

__device__ __forceinline__ uint32_t f2tf(float f) {
    uint32_t u;
    asm("cvt.rna.tf32.f32 %0, %1;" : "=r"(u) : "f"(f));
    return u;
}

// ---------------- dtype detection: int32 vs int64 edge_index -------------------
__global__ void detect_kernel(const int* __restrict__ ei_words) {
    __shared__ int nonzero;
    if (threadIdx.x == 0) nonzero = 0;
    __syncthreads();
    int w = ei_words[2 * threadIdx.x + 1];
    if (w != 0) atomicOr(&nonzero, 1);
    __syncthreads();
    if (threadIdx.x == 0) d_stride = nonzero ? 1 : 2;
}

// ---------------- zero per-launch state ----------------
__global__ void zero_kernel() {
    int i = blockIdx.x * blockDim.x + threadIdx.x;
    if (i < NN) { d_degcnt[i] = 0; d_cursor[i] = 0; }
    if (i < GG * OUTD) d_sums[i] = 0.0f;
    if (i < GG) d_cnt[i] = 0.0f;
}

// ---------------- in-degree count ----------------
__global__ void count_kernel(const int* __restrict__ ei) {
    int e = blockIdx.x * blockDim.x + threadIdx.x;
    if (e < EE) {
        int st = d_stride;
        int dst = clampi(ei[(size_t)st * (EE + e)], 0, NN - 1);
        atomicAdd(&d_degcnt[dst], 1);
    }
}

// ---------------- scan stages ----------------
__global__ __launch_bounds__(256) void scanA_kernel() {
    int i = blockIdx.x * 256 + threadIdx.x;
    int v = (i < NN) ? d_degcnt[i] : 0;
    int lane = threadIdx.x & 31, wid = threadIdx.x >> 5;
    int s = v;
    #pragma unroll
    for (int o = 16; o > 0; o >>= 1) s += __shfl_down_sync(0xffffffffu, s, o);
    __shared__ int ws[8];
    if (lane == 0) ws[wid] = s;
    __syncthreads();
    if (threadIdx.x == 0) {
        int t = 0;
        #pragma unroll
        for (int w = 0; w < 8; w++) t += ws[w];
        d_blksum[blockIdx.x] = t;
    }
}

__global__ __launch_bounds__(256) void scanB_kernel() {
    __shared__ int s_a[256], s_b[256];
    int t = threadIdx.x;
    int v = (t < NB) ? d_blksum[t] : 0;
    s_a[t] = v;
    __syncthreads();
    int* cur = s_a; int* nxt = s_b;
    for (int off = 1; off < 256; off <<= 1) {
        int x = cur[t];
        if (t >= off) x += cur[t - off];
        nxt[t] = x;
        __syncthreads();
        int* tmp = cur; cur = nxt; nxt = tmp;
    }
    if (t < NB) d_blkoff[t] = cur[t] - v;
    if (t == 0) d_rowptr[NN] = EE;
}

__global__ __launch_bounds__(256) void scanC_kernel() {
    int i = blockIdx.x * 256 + threadIdx.x;
    int v = (i < NN) ? d_degcnt[i] : 0;
    int lane = threadIdx.x & 31, wid = threadIdx.x >> 5;
    int incl = v;
    #pragma unroll
    for (int o = 1; o < 32; o <<= 1) {
        int y = __shfl_up_sync(0xffffffffu, incl, o);
        if (lane >= o) incl += y;
    }
    __shared__ int ws[8];
    if (lane == 31) ws[wid] = incl;
    __syncthreads();
    int woff = 0;
    #pragma unroll
    for (int w = 0; w < 8; w++) woff += (w < wid) ? ws[w] : 0;
    if (i < NN) {
        d_rowptr[i] = d_blkoff[blockIdx.x] + woff + incl - v;
        d_dinv[i] = rsqrtf(1.0f + (float)v);
    }
}

// ---------------- scatter edges into CSR buckets ----------------
__global__ void scatter_kernel(const int* __restrict__ ei) {
    int e = blockIdx.x * blockDim.x + threadIdx.x;
    if (e < EE) {
        int st = d_stride;
        int dst = clampi(ei[(size_t)st * (EE + e)], 0, NN - 1);
        int src = clampi(ei[(size_t)st * e],        0, NN - 1);
        int pos = d_rowptr[dst] + atomicAdd(&d_cursor[dst], 1);
        if (pos >= 0 && pos < EE) d_esrc[pos] = src;
    }
}

// ---------------- TF32 tensor-core GEMM ---------------------------------------
// C[n,128] = (A[n,128] @ B[128,128] + bias) * scale[row]
// 256 threads = 8 warps (2 m x 4 n), warp tile 32x32, mma.m16n8k8.tf32.
// A tile 64x128 in smem stride 132 (conflict-free frags); B in 16-row chunks
// stride 136 (conflict-free frags). fp32 accumulate.
__global__ __launch_bounds__(256) void gemm_tf32_kernel(
    const float* __restrict__ Aext, const float* __restrict__ B,
    const float* __restrict__ bias, int asel, int use_scale, int csel)
{
    __shared__ float As[64 * 132];   // 33792 B
    __shared__ float Bs[16 * 136];   //  8704 B

    const float* A = (asel == 0) ? Aext : (asel == 1 ? d_h0 : d_h1);
    float* C = (csel == 0) ? d_g : (csel == 1 ? d_h0 : d_h1);

    int tid = threadIdx.x;
    int wid = tid >> 5, lane = tid & 31;
    int g = lane >> 2, t = lane & 3;
    int wm = wid & 1, wn = wid >> 1;     // warp grid 2 x 4
    int row0 = blockIdx.x * 64;

    // load A tile (64 x 128) -> As stride 132; 2048 float4, 8 per thread
    {
        float4* As4 = (float4*)As;          // float4 stride = 33
        const float4* A4 = (const float4*)A;
        #pragma unroll
        for (int i = 0; i < 8; i++) {
            int idx = i * 256 + tid;
            int r = idx >> 5, c = idx & 31;
            int gr = row0 + r;
            As4[r * 33 + c] = (gr < NN) ? A4[(size_t)gr * 32 + c]
                                        : make_float4(0.f, 0.f, 0.f, 0.f);
        }
    }

    float acc[2][4][4];
    #pragma unroll
    for (int am = 0; am < 2; am++)
        #pragma unroll
        for (int an = 0; an < 4; an++)
            #pragma unroll
            for (int q = 0; q < 4; q++) acc[am][an][q] = 0.0f;

    const float4* B4 = (const float4*)B;
    float4* Bs4 = (float4*)Bs;              // float4 stride = 34

    for (int kc = 0; kc < 8; kc++) {
        __syncthreads();
        // load B rows [kc*16, kc*16+16): 512 float4, 2 per thread
        #pragma unroll
        for (int i = 0; i < 2; i++) {
            int idx = i * 256 + tid;
            int r = idx >> 5, c = idx & 31;
            Bs4[r * 34 + c] = B4[(size_t)(kc * 16 + r) * 32 + c];
        }
        __syncthreads();

        #pragma unroll
        for (int ka = 0; ka < 2; ka++) {
            int kcol = kc * 16 + ka * 8;    // global k of this atom
            int kb = ka * 8;                // k within chunk

            uint32_t a[2][4];
            #pragma unroll
            for (int am = 0; am < 2; am++) {
                int ar = wm * 32 + am * 16;
                const float* Ap = As + (size_t)(ar + g) * 132 + kcol + t;
                a[am][0] = f2tf(Ap[0]);
                a[am][1] = f2tf(Ap[8 * 132]);
                a[am][2] = f2tf(Ap[4]);
                a[am][3] = f2tf(Ap[8 * 132 + 4]);
            }
            uint32_t b[4][2];
            #pragma unroll
            for (int an = 0; an < 4; an++) {
                int bc = wn * 32 + an * 8 + g;
                b[an][0] = f2tf(Bs[(size_t)(kb + t) * 136 + bc]);
                b[an][1] = f2tf(Bs[(size_t)(kb + t + 4) * 136 + bc]);
            }
            #pragma unroll
            for (int am = 0; am < 2; am++)
                #pragma unroll
                for (int an = 0; an < 4; an++) {
                    asm volatile(
                        "mma.sync.aligned.m16n8k8.row.col.f32.tf32.tf32.f32 "
                        "{%0,%1,%2,%3}, {%4,%5,%6,%7}, {%8,%9}, {%0,%1,%2,%3};"
                        : "+f"(acc[am][an][0]), "+f"(acc[am][an][1]),
                          "+f"(acc[am][an][2]), "+f"(acc[am][an][3])
                        : "r"(a[am][0]), "r"(a[am][1]), "r"(a[am][2]), "r"(a[am][3]),
                          "r"(b[an][0]), "r"(b[an][1]));
                }
        }
    }

    // epilogue: c0:(g,2t) c1:(g,2t+1) c2:(g+8,2t) c3:(g+8,2t+1)
    #pragma unroll
    for (int am = 0; am < 2; am++) {
        int r0a = row0 + wm * 32 + am * 16;
        int rA = r0a + g;
        int rB = r0a + g + 8;
        float sA = 1.0f, sB = 1.0f;
        if (use_scale) {
            if (rA < NN) sA = d_dinv[rA];
            if (rB < NN) sB = d_dinv[rB];
        }
        #pragma unroll
        for (int an = 0; an < 4; an++) {
            int col = wn * 32 + an * 8 + 2 * t;
            float bx = bias ? bias[col]     : 0.0f;
            float by = bias ? bias[col + 1] : 0.0f;
            if (rA < NN) {
                float2 o;
                o.x = (acc[am][an][0] + bx) * sA;
                o.y = (acc[am][an][1] + by) * sA;
                *(float2*)(C + (size_t)rA * HH + col) = o;
            }
            if (rB < NN) {
                float2 o;
                o.x = (acc[am][an][2] + bx) * sB;
                o.y = (acc[am][an][3] + by) * sB;
                *(float2*)(C + (size_t)rB * HH + col) = o;
            }
        }
    }
}

// ---------------- neighborhood aggregation (gather-side, warp per node) --------
__global__ __launch_bounds__(256) void aggregate_kernel(
    const float* __restrict__ bias, int relu, int outsel)
{
    int node = blockIdx.x * 8 + (threadIdx.x >> 5);
    if (node >= NN) return;
    int lane = threadIdx.x & 31;
    float* out = (outsel == 1) ? d_h0 : d_h1;

    const float4* g4 = (const float4*)d_g;
    float4 acc = g4[(size_t)node * 32 + lane];   // self term

    int s = d_rowptr[node], e = d_rowptr[node + 1];
    for (int j = s; j < e; j += 32) {
        int src = (j + lane < e) ? d_esrc[j + lane] : 0;
        int cnt = min(32, e - j);
        for (int t = 0; t < cnt; t++) {
            int ss = __shfl_sync(0xffffffffu, src, t);
            float4 v = g4[(size_t)ss * 32 + lane];
            acc.x += v.x; acc.y += v.y; acc.z += v.z; acc.w += v.w;
        }
    }

    float di = d_dinv[node];
    float4 b4 = ((const float4*)bias)[lane];
    float4 o;
    o.x = fmaf(acc.x, di, b4.x);
    o.y = fmaf(acc.y, di, b4.y);
    o.z = fmaf(acc.z, di, b4.z);
    o.w = fmaf(acc.w, di, b4.w);
    if (relu) {
        o.x = fmaxf(o.x, 0.f); o.y = fmaxf(o.y, 0.f);
        o.z = fmaxf(o.z, 0.f); o.w = fmaxf(o.w, 0.f);
    }
    ((float4*)out)[(size_t)node * 32 + lane] = o;
}

// ---------------- classifier + global mean pool ----------------
__global__ __launch_bounds__(256) void cls_pool_kernel(
    const int* __restrict__ batch,
    const float* __restrict__ Wc, const float* __restrict__ bc, int hsel)
{
    __shared__ float sW[HH * OUTD];
    __shared__ float sB[OUTD];
    int tid = threadIdx.x;
    for (int i = tid; i < HH * OUTD; i += 256) sW[i] = Wc[i];
    if (tid < OUTD) sB[tid] = bc[tid];
    __syncthreads();

    const float* h = (hsel == 1) ? d_h0 : d_h1;
    int node = blockIdx.x * 8 + (tid >> 5);
    if (node >= NN) return;
    int lane = tid & 31;

    float hv[4];
    #pragma unroll
    for (int q = 0; q < 4; q++) hv[q] = h[(size_t)node * HH + q * 32 + lane];

    int d = (lane < OUTD) ? lane : 0;
    float acc = 0.0f;
    #pragma unroll 4
    for (int k = 0; k < 128; k++) {
        float hk = __shfl_sync(0xffffffffu, hv[k >> 5], k & 31);
        acc = fmaf(hk, sW[k * OUTD + d], acc);
    }
    int st = d_stride;
    int b = clampi(batch[(size_t)st * node], 0, GG - 1);
    if (lane < OUTD)  atomicAdd(&d_sums[b * OUTD + lane], acc + sB[lane]);
    if (lane == OUTD) atomicAdd(&d_cnt[b], 1.0f);
}

// ---------------- final divide ----------------
__global__ void finalize_kernel(float* __restrict__ out) {
    int i = blockIdx.x * blockDim.x + threadIdx.x;
    if (i < GG * OUTD) {
        float c = d_cnt[i / OUTD];
        out[i] = d_sums[i] / fmaxf(c, 1.0f);
    }
}

// ---------------- launch ----------------
extern "C" void kernel_launch(void* const* d_in, const int* in_sizes, int n_in,
                              void* d_out, int out_size) {
    const float* x      = (const float*)d_in[0];
    const int*   ei     = (const int*)d_in[1];
    const int*   batch  = (const int*)d_in[2];
    const float* W_in   = (const float*)d_in[3];
    const float* b_in   = (const float*)d_in[4];
    const float* W_hops = (const float*)d_in[5];
    const float* b_hops = (const float*)d_in[6];
    const float* W_cls  = (const float*)d_in[7];
    const float* b_cls  = (const float*)d_in[8];
    float* out = (float*)d_out;

    detect_kernel<<<1, 128>>>(ei);
    zero_kernel<<<(NN + 255) / 256, 256>>>();
    count_kernel<<<(EE + 255) / 256, 256>>>(ei);
    scanA_kernel<<<NB, 256>>>();
    scanB_kernel<<<1, 256>>>();
    scanC_kernel<<<NB, 256>>>();
    scatter_kernel<<<(EE + 255) / 256, 256>>>(ei);

    const int GB = (NN + 63) / 64;
    gemm_tf32_kernel<<<GB, 256>>>(x, W_in, b_in, 0, 0, 1);

    int cur = 1;   // d_h0
    for (int hop = 0; hop < NHOPS; hop++) {
        int nxt = (cur == 1) ? 2 : 1;
        gemm_tf32_kernel<<<GB, 256>>>(nullptr, W_hops + (size_t)hop * HH * HH,
                                      nullptr, cur, 1, 0);
        aggregate_kernel<<<(NN + 7) / 8, 256>>>(b_hops + hop * HH,
                                                hop < NHOPS - 1 ? 1 : 0, nxt);
        cur = nxt;
    }

    cls_pool_kernel<<<(NN + 7) / 8, 256>>>(batch, W_cls, b_cls, cur);
    finalize_kernel<<<(GG * OUTD + 255) / 256, 256>>>(out);
}

// round 9
// speedup vs baseline: 2.2148x; 1.1470x over previous
#include <cuda_runtime.h>
#include <cstdint>

#define NN    50000
#define EE    800000
#define HH    128
#define GG    128
#define OUTD  10
#define NHOPS 4
#define NB    ((NN + 255) / 256)   // 196 scan blocks

// ---------------- device scratch (static, no runtime allocation) ----------------
__device__ __align__(16) float d_h0[NN * HH];
__device__ __align__(16) float d_h1[NN * HH];
__device__ __align__(16) float d_g[NN * HH];
__device__ float d_dinv[NN];
__device__ int   d_degcnt[NN];
__device__ int   d_rowptr[NN + 1];
__device__ int   d_cursor[NN];
__device__ int   d_esrc[EE];
__device__ float d_sums[GG * OUTD];
__device__ float d_cnt[GG];
__device__ int   d_stride;     // 1 = int32 inputs, 2 = int64 inputs
__device__ int   d_blksum[NB];
__device__ int   d_blkoff[NB];

__device__ __forceinline__ int clampi(int v, int lo, int hi) {
    return v < lo ? lo : (v > hi ? hi : v);
}

__device__ __forceinline__ uint32_t f2tf(float f) {
    uint32_t u;
    asm("cvt.rna.tf32.f32 %0, %1;" : "=r"(u) : "f"(f));
    return u;
}

// ---------------- dtype detection: int32 vs int64 edge_index -------------------
__global__ void detect_kernel(const int* __restrict__ ei_words) {
    __shared__ int nonzero;
    if (threadIdx.x == 0) nonzero = 0;
    __syncthreads();
    int w = ei_words[2 * threadIdx.x + 1];
    if (w != 0) atomicOr(&nonzero, 1);
    __syncthreads();
    if (threadIdx.x == 0) d_stride = nonzero ? 1 : 2;
}

// ---------------- zero per-launch state ----------------
__global__ void zero_kernel() {
    int i = blockIdx.x * blockDim.x + threadIdx.x;
    if (i < NN) { d_degcnt[i] = 0; d_cursor[i] = 0; }
    if (i < GG * OUTD) d_sums[i] = 0.0f;
    if (i < GG) d_cnt[i] = 0.0f;
}

// ---------------- in-degree count ----------------
__global__ void count_kernel(const int* __restrict__ ei) {
    int e = blockIdx.x * blockDim.x + threadIdx.x;
    if (e < EE) {
        int st = d_stride;
        int dst = clampi(ei[(size_t)st * (EE + e)], 0, NN - 1);
        atomicAdd(&d_degcnt[dst], 1);
    }
}

// ---------------- scan stages ----------------
__global__ __launch_bounds__(256) void scanA_kernel() {
    int i = blockIdx.x * 256 + threadIdx.x;
    int v = (i < NN) ? d_degcnt[i] : 0;
    int lane = threadIdx.x & 31, wid = threadIdx.x >> 5;
    int s = v;
    #pragma unroll
    for (int o = 16; o > 0; o >>= 1) s += __shfl_down_sync(0xffffffffu, s, o);
    __shared__ int ws[8];
    if (lane == 0) ws[wid] = s;
    __syncthreads();
    if (threadIdx.x == 0) {
        int t = 0;
        #pragma unroll
        for (int w = 0; w < 8; w++) t += ws[w];
        d_blksum[blockIdx.x] = t;
    }
}

__global__ __launch_bounds__(256) void scanB_kernel() {
    __shared__ int s_a[256], s_b[256];
    int t = threadIdx.x;
    int v = (t < NB) ? d_blksum[t] : 0;
    s_a[t] = v;
    __syncthreads();
    int* cur = s_a; int* nxt = s_b;
    for (int off = 1; off < 256; off <<= 1) {
        int x = cur[t];
        if (t >= off) x += cur[t - off];
        nxt[t] = x;
        __syncthreads();
        int* tmp = cur; cur = nxt; nxt = tmp;
    }
    if (t < NB) d_blkoff[t] = cur[t] - v;
    if (t == 0) d_rowptr[NN] = EE;
}

__global__ __launch_bounds__(256) void scanC_kernel() {
    int i = blockIdx.x * 256 + threadIdx.x;
    int v = (i < NN) ? d_degcnt[i] : 0;
    int lane = threadIdx.x & 31, wid = threadIdx.x >> 5;
    int incl = v;
    #pragma unroll
    for (int o = 1; o < 32; o <<= 1) {
        int y = __shfl_up_sync(0xffffffffu, incl, o);
        if (lane >= o) incl += y;
    }
    __shared__ int ws[8];
    if (lane == 31) ws[wid] = incl;
    __syncthreads();
    int woff = 0;
    #pragma unroll
    for (int w = 0; w < 8; w++) woff += (w < wid) ? ws[w] : 0;
    if (i < NN) {
        d_rowptr[i] = d_blkoff[blockIdx.x] + woff + incl - v;
        d_dinv[i] = rsqrtf(1.0f + (float)v);
    }
}

// ---------------- scatter edges into CSR buckets ----------------
__global__ void scatter_kernel(const int* __restrict__ ei) {
    int e = blockIdx.x * blockDim.x + threadIdx.x;
    if (e < EE) {
        int st = d_stride;
        int dst = clampi(ei[(size_t)st * (EE + e)], 0, NN - 1);
        int src = clampi(ei[(size_t)st * e],        0, NN - 1);
        int pos = d_rowptr[dst] + atomicAdd(&d_cursor[dst], 1);
        if (pos >= 0 && pos < EE) d_esrc[pos] = src;
    }
}

// ---------------- TF32 tensor-core GEMM ---------------------------------------
__global__ __launch_bounds__(256) void gemm_tf32_kernel(
    const float* __restrict__ Aext, const float* __restrict__ B,
    const float* __restrict__ bias, int asel, int use_scale, int csel)
{
    __shared__ float As[64 * 132];   // 33792 B
    __shared__ float Bs[16 * 136];   //  8704 B

    const float* A = (asel == 0) ? Aext : (asel == 1 ? d_h0 : d_h1);
    float* C = (csel == 0) ? d_g : (csel == 1 ? d_h0 : d_h1);

    int tid = threadIdx.x;
    int wid = tid >> 5, lane = tid & 31;
    int g = lane >> 2, t = lane & 3;
    int wm = wid & 1, wn = wid >> 1;     // warp grid 2 x 4
    int row0 = blockIdx.x * 64;

    {
        float4* As4 = (float4*)As;          // float4 stride = 33
        const float4* A4 = (const float4*)A;
        #pragma unroll
        for (int i = 0; i < 8; i++) {
            int idx = i * 256 + tid;
            int r = idx >> 5, c = idx & 31;
            int gr = row0 + r;
            As4[r * 33 + c] = (gr < NN) ? A4[(size_t)gr * 32 + c]
                                        : make_float4(0.f, 0.f, 0.f, 0.f);
        }
    }

    float acc[2][4][4];
    #pragma unroll
    for (int am = 0; am < 2; am++)
        #pragma unroll
        for (int an = 0; an < 4; an++)
            #pragma unroll
            for (int q = 0; q < 4; q++) acc[am][an][q] = 0.0f;

    const float4* B4 = (const float4*)B;
    float4* Bs4 = (float4*)Bs;              // float4 stride = 34

    for (int kc = 0; kc < 8; kc++) {
        __syncthreads();
        #pragma unroll
        for (int i = 0; i < 2; i++) {
            int idx = i * 256 + tid;
            int r = idx >> 5, c = idx & 31;
            Bs4[r * 34 + c] = B4[(size_t)(kc * 16 + r) * 32 + c];
        }
        __syncthreads();

        #pragma unroll
        for (int ka = 0; ka < 2; ka++) {
            int kcol = kc * 16 + ka * 8;
            int kb = ka * 8;

            uint32_t a[2][4];
            #pragma unroll
            for (int am = 0; am < 2; am++) {
                int ar = wm * 32 + am * 16;
                const float* Ap = As + (size_t)(ar + g) * 132 + kcol + t;
                a[am][0] = f2tf(Ap[0]);
                a[am][1] = f2tf(Ap[8 * 132]);
                a[am][2] = f2tf(Ap[4]);
                a[am][3] = f2tf(Ap[8 * 132 + 4]);
            }
            uint32_t b[4][2];
            #pragma unroll
            for (int an = 0; an < 4; an++) {
                int bc = wn * 32 + an * 8 + g;
                b[an][0] = f2tf(Bs[(size_t)(kb + t) * 136 + bc]);
                b[an][1] = f2tf(Bs[(size_t)(kb + t + 4) * 136 + bc]);
            }
            #pragma unroll
            for (int am = 0; am < 2; am++)
                #pragma unroll
                for (int an = 0; an < 4; an++) {
                    asm volatile(
                        "mma.sync.aligned.m16n8k8.row.col.f32.tf32.tf32.f32 "
                        "{%0,%1,%2,%3}, {%4,%5,%6,%7}, {%8,%9}, {%0,%1,%2,%3};"
                        : "+f"(acc[am][an][0]), "+f"(acc[am][an][1]),
                          "+f"(acc[am][an][2]), "+f"(acc[am][an][3])
                        : "r"(a[am][0]), "r"(a[am][1]), "r"(a[am][2]), "r"(a[am][3]),
                          "r"(b[an][0]), "r"(b[an][1]));
                }
        }
    }

    #pragma unroll
    for (int am = 0; am < 2; am++) {
        int r0a = row0 + wm * 32 + am * 16;
        int rA = r0a + g;
        int rB = r0a + g + 8;
        float sA = 1.0f, sB = 1.0f;
        if (use_scale) {
            if (rA < NN) sA = d_dinv[rA];
            if (rB < NN) sB = d_dinv[rB];
        }
        #pragma unroll
        for (int an = 0; an < 4; an++) {
            int col = wn * 32 + an * 8 + 2 * t;
            float bx = bias ? bias[col]     : 0.0f;
            float by = bias ? bias[col + 1] : 0.0f;
            if (rA < NN) {
                float2 o;
                o.x = (acc[am][an][0] + bx) * sA;
                o.y = (acc[am][an][1] + by) * sA;
                *(float2*)(C + (size_t)rA * HH + col) = o;
            }
            if (rB < NN) {
                float2 o;
                o.x = (acc[am][an][2] + bx) * sB;
                o.y = (acc[am][an][3] + by) * sB;
                *(float2*)(C + (size_t)rB * HH + col) = o;
            }
        }
    }
}

// ---------------- neighborhood aggregation (warp per node, MLP=4) --------------
__global__ __launch_bounds__(256) void aggregate_kernel(
    const float* __restrict__ bias, int relu, int outsel)
{
    int node = blockIdx.x * 8 + (threadIdx.x >> 5);
    if (node >= NN) return;
    int lane = threadIdx.x & 31;
    float* out = (outsel == 1) ? d_h0 : d_h1;

    const float4* g4 = (const float4*)d_g;
    float4 acc = g4[(size_t)node * 32 + lane];   // self term

    int s = d_rowptr[node], e = d_rowptr[node + 1];
    int j = s;
    for (; j + 3 < e; j += 4) {
        int s0 = d_esrc[j], s1 = d_esrc[j + 1], s2 = d_esrc[j + 2], s3 = d_esrc[j + 3];
        float4 v0 = g4[(size_t)s0 * 32 + lane];
        float4 v1 = g4[(size_t)s1 * 32 + lane];
        float4 v2 = g4[(size_t)s2 * 32 + lane];
        float4 v3 = g4[(size_t)s3 * 32 + lane];
        acc.x += v0.x + v1.x + v2.x + v3.x;
        acc.y += v0.y + v1.y + v2.y + v3.y;
        acc.z += v0.z + v1.z + v2.z + v3.z;
        acc.w += v0.w + v1.w + v2.w + v3.w;
    }
    for (; j < e; j++) {
        int ss = d_esrc[j];
        float4 v = g4[(size_t)ss * 32 + lane];
        acc.x += v.x; acc.y += v.y; acc.z += v.z; acc.w += v.w;
    }

    float di = d_dinv[node];
    float4 b4 = ((const float4*)bias)[lane];
    float4 o;
    o.x = fmaf(acc.x, di, b4.x);
    o.y = fmaf(acc.y, di, b4.y);
    o.z = fmaf(acc.z, di, b4.z);
    o.w = fmaf(acc.w, di, b4.w);
    if (relu) {
        o.x = fmaxf(o.x, 0.f); o.y = fmaxf(o.y, 0.f);
        o.z = fmaxf(o.z, 0.f); o.w = fmaxf(o.w, 0.f);
    }
    ((float4*)out)[(size_t)node * 32 + lane] = o;
}

// ---------------- fused last-hop aggregation + classifier + pool ----------------
// out-row never materialized: o = dinv*(self+sum)+bias, then y = o @ Wc + bc,
// pooled into d_sums via atomics.
__global__ __launch_bounds__(256) void aggregate_cls_kernel(
    const float* __restrict__ bias, const int* __restrict__ batch,
    const float* __restrict__ Wc, const float* __restrict__ bc)
{
    __shared__ float sW[HH * OUTD];
    __shared__ float sB[OUTD];
    int tid = threadIdx.x;
    for (int i = tid; i < HH * OUTD; i += 256) sW[i] = Wc[i];
    if (tid < OUTD) sB[tid] = bc[tid];
    __syncthreads();

    int node = blockIdx.x * 8 + (tid >> 5);
    if (node >= NN) return;
    int lane = tid & 31;

    const float4* g4 = (const float4*)d_g;
    float4 acc = g4[(size_t)node * 32 + lane];

    int s = d_rowptr[node], e = d_rowptr[node + 1];
    int j = s;
    for (; j + 3 < e; j += 4) {
        int s0 = d_esrc[j], s1 = d_esrc[j + 1], s2 = d_esrc[j + 2], s3 = d_esrc[j + 3];
        float4 v0 = g4[(size_t)s0 * 32 + lane];
        float4 v1 = g4[(size_t)s1 * 32 + lane];
        float4 v2 = g4[(size_t)s2 * 32 + lane];
        float4 v3 = g4[(size_t)s3 * 32 + lane];
        acc.x += v0.x + v1.x + v2.x + v3.x;
        acc.y += v0.y + v1.y + v2.y + v3.y;
        acc.z += v0.z + v1.z + v2.z + v3.z;
        acc.w += v0.w + v1.w + v2.w + v3.w;
    }
    for (; j < e; j++) {
        int ss = d_esrc[j];
        float4 v = g4[(size_t)ss * 32 + lane];
        acc.x += v.x; acc.y += v.y; acc.z += v.z; acc.w += v.w;
    }

    float di = d_dinv[node];
    float4 b4 = ((const float4*)bias)[lane];
    float4 o;                      // cols 4*lane .. 4*lane+3 (no relu on last hop)
    o.x = fmaf(acc.x, di, b4.x);
    o.y = fmaf(acc.y, di, b4.y);
    o.z = fmaf(acc.z, di, b4.z);
    o.w = fmaf(acc.w, di, b4.w);

    // classifier partials: p[d] = sum over this lane's 4 cols
    int c0 = 4 * lane;
    float p[OUTD];
    #pragma unroll
    for (int d = 0; d < OUTD; d++) {
        float v = o.x * sW[(c0 + 0) * OUTD + d];
        v = fmaf(o.y, sW[(c0 + 1) * OUTD + d], v);
        v = fmaf(o.z, sW[(c0 + 2) * OUTD + d], v);
        v = fmaf(o.w, sW[(c0 + 3) * OUTD + d], v);
        p[d] = v;
    }
    // butterfly reduce each of the 10 values (result in all lanes)
    #pragma unroll
    for (int off = 16; off > 0; off >>= 1) {
        #pragma unroll
        for (int d = 0; d < OUTD; d++)
            p[d] += __shfl_xor_sync(0xffffffffu, p[d], off);
    }
    int st = d_stride;
    int b = clampi(batch[(size_t)st * node], 0, GG - 1);
    if (lane < OUTD) {
        float v = p[0];
        #pragma unroll
        for (int d = 1; d < OUTD; d++) v = (lane == d) ? p[d] : v;
        atomicAdd(&d_sums[b * OUTD + lane], v + sB[lane]);
    }
    if (lane == OUTD) atomicAdd(&d_cnt[b], 1.0f);
}

// ---------------- final divide ----------------
__global__ void finalize_kernel(float* __restrict__ out) {
    int i = blockIdx.x * blockDim.x + threadIdx.x;
    if (i < GG * OUTD) {
        float c = d_cnt[i / OUTD];
        out[i] = d_sums[i] / fmaxf(c, 1.0f);
    }
}

// ---------------- launch ----------------
extern "C" void kernel_launch(void* const* d_in, const int* in_sizes, int n_in,
                              void* d_out, int out_size) {
    const float* x      = (const float*)d_in[0];
    const int*   ei     = (const int*)d_in[1];
    const int*   batch  = (const int*)d_in[2];
    const float* W_in   = (const float*)d_in[3];
    const float* b_in   = (const float*)d_in[4];
    const float* W_hops = (const float*)d_in[5];
    const float* b_hops = (const float*)d_in[6];
    const float* W_cls  = (const float*)d_in[7];
    const float* b_cls  = (const float*)d_in[8];
    float* out = (float*)d_out;

    const int GB = (NN + 63) / 64;

    detect_kernel<<<1, 128>>>(ei);
    zero_kernel<<<(NN + 255) / 256, 256>>>();
    count_kernel<<<(EE + 255) / 256, 256>>>(ei);
    // encoder GEMM in slot 4 (independent of scans) -> gets ncu-profiled
    gemm_tf32_kernel<<<GB, 256>>>(x, W_in, b_in, 0, 0, 1);
    scanA_kernel<<<NB, 256>>>();
    scanB_kernel<<<1, 256>>>();
    scanC_kernel<<<NB, 256>>>();
    scatter_kernel<<<(EE + 255) / 256, 256>>>(ei);

    int cur = 1;   // d_h0
    for (int hop = 0; hop < NHOPS; hop++) {
        int nxt = (cur == 1) ? 2 : 1;
        gemm_tf32_kernel<<<GB, 256>>>(nullptr, W_hops + (size_t)hop * HH * HH,
                                      nullptr, cur, 1, 0);
        if (hop < NHOPS - 1) {
            aggregate_kernel<<<(NN + 7) / 8, 256>>>(b_hops + hop * HH, 1, nxt);
        } else {
            aggregate_cls_kernel<<<(NN + 7) / 8, 256>>>(b_hops + hop * HH,
                                                        batch, W_cls, b_cls);
        }
        cur = nxt;
    }

    finalize_kernel<<<(GG * OUTD + 255) / 256, 256>>>(out);
}